// round 4
// baseline (speedup 1.0000x reference)
#include <cuda_runtime.h>
#include <cstdint>

// ---------------------------------------------------------------------------
#define M_MODES 10
#define N_PHOT  5
#define N_NB    252     // C(10,5)
#define N_B     2002    // C(14,5)
#define MAX_B   256
#define SPLIT   4       // blocks per batch element in qc_main

typedef unsigned long long ull;

// __device__ global tables (no allocations allowed)
__device__ float2 g_WR1[10][10];
__device__ float2 g_WL1c[10][5];   // WL1[:, IN_MODES]
__device__ float2 g_WRF[10][10];
__device__ float2 g_WLFc[10][5];   // WLF[:, IN_MODES]
__device__ unsigned g_rows_nb[N_NB];   // 5 modes packed 4 bits each
__device__ unsigned g_rows_b[N_B];
__device__ float    g_inv_norm_b[N_B];
__device__ float    g_partial[MAX_B][SPLIT][10];
__device__ int      g_cnt[MAX_B];

// ---------------------------------------------------------------------------
// packed f32x2 helpers (sm_103a FFMA2 path)
// ---------------------------------------------------------------------------
__device__ __forceinline__ ull pk(float lo, float hi) {
    ull r; asm("mov.b64 %0, {%1, %2};" : "=l"(r) : "f"(lo), "f"(hi)); return r;
}
__device__ __forceinline__ float2 unpk(ull v) {
    float2 f; asm("mov.b64 {%0, %1}, %2;" : "=f"(f.x), "=f"(f.y) : "l"(v)); return f;
}
__device__ __forceinline__ ull fma2(ull a, ull b, ull c) {
    ull r; asm("fma.rn.f32x2 %0, %1, %2, %3;" : "=l"(r) : "l"(a), "l"(b), "l"(c)); return r;
}
__device__ __forceinline__ ull add2(ull a, ull b) {
    ull r; asm("add.rn.f32x2 %0, %1, %2;" : "=l"(r) : "l"(a), "l"(b)); return r;
}

__device__ __forceinline__ float2 cmul(float2 a, float2 b) {
    return make_float2(fmaf(a.x, b.x, -a.y * b.y), fmaf(a.x, b.y, a.y * b.x));
}
__device__ __forceinline__ float2 cadd(float2 a, float2 b) {
    return make_float2(a.x + b.x, a.y + b.y);
}

__device__ __forceinline__ long binom(int n, int k) {
    if (k < 0 || n < 0 || k > n) return 0;
    long r = 1;
    for (int i = 1; i <= k; i++) r = r * (n - k + i) / i;
    return r;
}

// ---------------------------------------------------------------------------
// Setup: interferometers + Fock tables + per-batch counters.
// grid: 11 blocks x 256 threads.
// ---------------------------------------------------------------------------
__global__ void setup_kernel(const float* __restrict__ ph_l1,
                             const float* __restrict__ ph_r1,
                             const float* __restrict__ ph_lf,
                             const float* __restrict__ ph_rf) {
    if (blockIdx.x == 10) {
        if (threadIdx.x < MAX_B) g_cnt[threadIdx.x] = 0;
        return;
    }
    if (blockIdx.x == 0) {
        __shared__ float2 T[4][45][4];
        int t = threadIdx.x;
        if (t < 180) {
            int g = t / 45, k = t % 45;
            const float* ph = (g == 0) ? ph_l1 : (g == 1) ? ph_r1 : (g == 2) ? ph_lf : ph_rf;
            float t1 = ph[2 * k], t2 = ph[2 * k + 1];
            float s1, c1, s2, c2v;
            sincosf(t1, &s1, &c1);
            sincosf(t2, &s2, &c2v);
            float2 e1 = make_float2(c1, s1), e2 = make_float2(c2v, s2);
            const float s = 0.7071067811865476f;
            float2 B00 = make_float2(s, 0), B01 = make_float2(0, s);
            float2 B10 = make_float2(0, s), B11 = make_float2(s, 0);
            float2 M100 = cmul(e1, B00), M101 = cmul(e1, B01);
            float2 M110 = B10, M111 = B11;
            float2 M200 = cadd(cmul(B00, M100), cmul(B01, M110));
            float2 M201 = cadd(cmul(B00, M101), cmul(B01, M111));
            float2 M210 = cadd(cmul(B10, M100), cmul(B11, M110));
            float2 M211 = cadd(cmul(B10, M101), cmul(B11, M111));
            T[g][k][0] = cmul(e2, M200);
            T[g][k][1] = cmul(e2, M201);
            T[g][k][2] = M210;
            T[g][k][3] = M211;
        }
        __syncthreads();
        if (t < 40) {
            int g = t / 10, col = t % 10;
            float2 u[10];
            #pragma unroll
            for (int m = 0; m < 10; m++) u[m] = make_float2(m == col ? 1.f : 0.f, 0.f);
            int k = 0;
            for (int layer = 0; layer < 10; layer++) {
                for (int p = (layer & 1); p < 9; p += 2) {
                    float2 a = u[p], b = u[p + 1];
                    u[p]     = cadd(cmul(T[g][k][0], a), cmul(T[g][k][1], b));
                    u[p + 1] = cadd(cmul(T[g][k][2], a), cmul(T[g][k][3], b));
                    k++;
                }
            }
            if (g == 0) {
                if ((col & 1) == 0)
                    for (int m = 0; m < 10; m++) g_WL1c[m][col >> 1] = u[m];
            } else if (g == 1) {
                for (int m = 0; m < 10; m++) g_WR1[m][col] = u[m];
            } else if (g == 2) {
                if ((col & 1) == 0)
                    for (int m = 0; m < 10; m++) g_WLFc[m][col >> 1] = u[m];
            } else {
                for (int m = 0; m < 10; m++) g_WRF[m][col] = u[m];
            }
        }
    } else {
        int idx = (blockIdx.x - 1) * blockDim.x + threadIdx.x;
        if (idx < N_NB) {
            int r = idx, x = 0;
            unsigned packed = 0;
            for (int pos = 0; pos < 5; pos++) {
                for (;;) {
                    long cnt = binom(9 - x, 4 - pos);
                    if (r < cnt) break;
                    r -= (int)cnt;
                    x++;
                }
                packed |= (unsigned)x << (4 * pos);
                x++;
            }
            g_rows_nb[idx] = packed;
        } else if (idx < N_NB + N_B) {
            int rank = idx - N_NB;
            int r = rank, x = 0;
            int row[5];
            for (int pos = 0; pos < 5; pos++) {
                for (;;) {
                    long cnt = binom(13 - x, 4 - pos);
                    if (r < cnt) break;
                    r -= (int)cnt;
                    x++;
                }
                row[pos] = x - pos;
                x++;
            }
            unsigned packed = 0;
            int cnt_[10];
            #pragma unroll
            for (int m = 0; m < 10; m++) cnt_[m] = 0;
            #pragma unroll
            for (int pos = 0; pos < 5; pos++) {
                packed |= (unsigned)row[pos] << (4 * pos);
                cnt_[row[pos]]++;
            }
            const float fact[6] = {1.f, 1.f, 2.f, 6.f, 24.f, 120.f};
            float norm = 1.f;
            #pragma unroll
            for (int m = 0; m < 10; m++) norm *= fact[cnt_[m]];
            g_rows_b[rank] = packed;
            g_inv_norm_b[rank] = 1.0f / norm;
        }
    }
}

// ---------------------------------------------------------------------------
// Glynn |perm|^2 with packed-f32x2 rowsum init/update; scalar product tree.
// V: shared 10x5 packed complex. packed: 5 row indices, 4 bits each.
// ---------------------------------------------------------------------------
__device__ __forceinline__ float perm_prob(const ull (*__restrict__ V)[5], unsigned packed) {
    ull M[5][5];
    #pragma unroll
    for (int i = 0; i < 5; i++) {
        int ri = (packed >> (4 * i)) & 15;
        #pragma unroll
        for (int j = 0; j < 5; j++) M[i][j] = V[ri][j];
    }
    ull rs[5];
    #pragma unroll
    for (int j = 0; j < 5; j++)
        rs[j] = add2(add2(add2(M[0][j], M[1][j]), add2(M[2][j], M[3][j])), M[4][j]);

    const ull P2 = 0x4000000040000000ULL;  // (+2, +2)
    const ull N2 = 0xC0000000C0000000ULL;  // (-2, -2)
    float sx = 0.f, sy = 0.f;
    #pragma unroll
    for (int g = 0; g < 16; g++) {
        float2 r0 = unpk(rs[0]), r1 = unpk(rs[1]), r2 = unpk(rs[2]);
        float2 r3 = unpk(rs[3]), r4 = unpk(rs[4]);
        float2 p01 = cmul(r0, r1);
        float2 p23 = cmul(r2, r3);
        float2 p = cmul(cmul(p01, p23), r4);
        if (g & 1) { sx -= p.x; sy -= p.y; }
        else       { sx += p.x; sy += p.y; }
        if (g < 15) {
            int gc = g ^ (g >> 1);
            int gn = (g + 1) ^ ((g + 1) >> 1);
            int diff = gc ^ gn;         // single bit, compile-time per g
            int i = __ffs(diff);        // = bit+1 = row index to flip
            ull D = (gn & diff) ? N2 : P2;
            #pragma unroll
            for (int j = 0; j < 5; j++) rs[j] = fma2(D, M[i][j], rs[j]);
        }
    }
    sx *= 0.0625f;
    sy *= 0.0625f;
    return fmaf(sx, sx, sy * sy);
}

// ---------------------------------------------------------------------------
// Fused main: SPLIT blocks per batch element. All compute stage 1; each does
// 1/SPLIT of the 2002 bunched perms; last-arriving block combines partials
// in fixed order (bitwise deterministic).
// ---------------------------------------------------------------------------
__global__ __launch_bounds__(256, 3)
void qc_main(const float* __restrict__ x, const float* __restrict__ Wd,
             const float* __restrict__ bd, const float* __restrict__ Wo,
             const float* __restrict__ bo, float* __restrict__ out) {
    int bid = blockIdx.x;
    int b = bid >> 2;          // / SPLIT
    int s = bid & (SPLIT - 1);
    int t = threadIdx.x;
    int lane = t & 31;
    int w = t >> 5;  // 8 warps

    __shared__ float2 sh_eih[10];
    __shared__ ull    sh_V[10][5];
    __shared__ float  sh_e1[N_NB];
    __shared__ float  sh_red[8][10];
    __shared__ int    sh_last;

    // 1. h = (x@Wd + bd)/pi : warp w handles modes w (and w+8 for w<2)
    for (int mode = w; mode < 10; mode += 8) {
        float acc = 0.f;
        const float* xb = x + b * 784;
        for (int i = lane; i < 784; i += 32) acc = fmaf(xb[i], Wd[i * 10 + mode], acc);
        #pragma unroll
        for (int o = 16; o; o >>= 1) acc += __shfl_xor_sync(0xffffffffu, acc, o);
        if (lane == 0) {
            float h = (acc + bd[mode]) * 0.3183098861837907f;  // 1/pi
            float sn, cs;
            sincosf(h, &sn, &cs);
            sh_eih[mode] = make_float2(cs, sn);
        }
    }
    __syncthreads();

    // 2. V1[m][j] = sum_k WR1[m][k] * e^{ih_k} * WL1c[k][j]
    if (t < 50) {
        int m = t / 5, j = t % 5;
        float2 v = make_float2(0.f, 0.f);
        #pragma unroll
        for (int k = 0; k < 10; k++)
            v = cadd(v, cmul(g_WR1[m][k], cmul(sh_eih[k], g_WL1c[k][j])));
        sh_V[m][j] = pk(v.x, v.y);
    }
    __syncthreads();

    // 3. 252 no-bunching probabilities (norm = 1)
    if (t < N_NB) sh_e1[t] = perm_prob(sh_V, g_rows_nb[t]);
    __syncthreads();

    // 4. phi2[m] = sum_j e1[m + 10j]; then e^{i phi2}
    if (t < 10) {
        float phi = 0.f;
        #pragma unroll
        for (int j2 = 0; j2 < 25; j2++) phi += sh_e1[t + 10 * j2];
        phi += (t < 2) ? sh_e1[t + 250] : 0.f;
        float sn, cs;
        sincosf(phi, &sn, &cs);
        sh_eih[t] = make_float2(cs, sn);
    }
    __syncthreads();

    // 5. VF[m][j]
    if (t < 50) {
        int m = t / 5, j = t % 5;
        float2 v = make_float2(0.f, 0.f);
        #pragma unroll
        for (int k = 0; k < 10; k++)
            v = cadd(v, cmul(g_WRF[m][k], cmul(sh_eih[k], g_WLFc[k][j])));
        sh_V[m][j] = pk(v.x, v.y);
    }
    __syncthreads();

    // 6. this block's quarter of the 2002 bunched perms, fused with probs@W_out
    ull acc5[5] = {0, 0, 0, 0, 0};
    #pragma unroll
    for (int iter = 0; iter < 2; iter++) {
        int k = s + SPLIT * (iter * 256 + t);
        if (k < N_B) {
            float p = perm_prob(sh_V, g_rows_b[k]) * g_inv_norm_b[k];
            ull p2 = pk(p, p);
            const ull* wr = (const ull*)(Wo + k * 10);   // 40B row -> 8B aligned
            #pragma unroll
            for (int c = 0; c < 5; c++) acc5[c] = fma2(p2, wr[c], acc5[c]);
        }
    }

    #pragma unroll
    for (int c = 0; c < 5; c++) {
        float2 v = unpk(acc5[c]);
        #pragma unroll
        for (int o = 16; o; o >>= 1) {
            v.x += __shfl_xor_sync(0xffffffffu, v.x, o);
            v.y += __shfl_xor_sync(0xffffffffu, v.y, o);
        }
        if (lane == 0) { sh_red[w][2 * c] = v.x; sh_red[w][2 * c + 1] = v.y; }
    }
    __syncthreads();

    // block partial -> global
    if (t < 10) {
        float v = 0.f;
        #pragma unroll
        for (int ww = 0; ww < 8; ww++) v += sh_red[ww][t];
        g_partial[b][s][t] = v;
    }
    __threadfence();
    __syncthreads();
    if (t == 0) {
        int done = atomicAdd(&g_cnt[b], 1);
        sh_last = (done == SPLIT - 1);
    }
    __syncthreads();
    if (sh_last) {
        __threadfence();
        if (t < 10) {
            float v = bo[t];
            #pragma unroll
            for (int s4 = 0; s4 < SPLIT; s4++) v += g_partial[b][s4][t];
            out[b * 10 + t] = v;
        }
    }
}

// ---------------------------------------------------------------------------
extern "C" void kernel_launch(void* const* d_in, const int* in_sizes, int n_in,
                              void* d_out, int out_size) {
    const float* x   = (const float*)d_in[0];
    const float* Wd  = (const float*)d_in[1];
    const float* bd  = (const float*)d_in[2];
    const float* pl1 = (const float*)d_in[3];
    const float* pr1 = (const float*)d_in[4];
    const float* plf = (const float*)d_in[5];
    const float* prf = (const float*)d_in[6];
    const float* Wo  = (const float*)d_in[7];
    const float* bo  = (const float*)d_in[8];
    float* out = (float*)d_out;

    int B = in_sizes[0] / 784;

    setup_kernel<<<11, 256>>>(pl1, pr1, plf, prf);
    qc_main<<<SPLIT * B, 256>>>(x, Wd, bd, Wo, bo, out);
}

// round 5
// speedup vs baseline: 1.6486x; 1.6486x over previous
#include <cuda_runtime.h>
#include <cstdint>

// ---------------------------------------------------------------------------
#define M_MODES 10
#define N_PHOT  5
#define N_NB    252     // C(10,5)
#define N_B     2002    // C(14,5)

// __device__ global tables (no allocations allowed)
__device__ float2 g_WR1[10][10];
__device__ float2 g_WL1c[10][5];   // WL1[:, IN_MODES]
__device__ float2 g_WRF[10][10];
__device__ float2 g_WLFc[10][5];   // WLF[:, IN_MODES]
__device__ unsigned g_rows_nb[N_NB];   // 5 modes packed 4 bits each
__device__ unsigned g_rows_b[N_B];
__device__ float    g_inv_norm_b[N_B];

// ---------------------------------------------------------------------------
__device__ __forceinline__ float2 cmul(float2 a, float2 b) {
    return make_float2(fmaf(a.x, b.x, -a.y * b.y), fmaf(a.x, b.y, a.y * b.x));
}
__device__ __forceinline__ float2 cadd(float2 a, float2 b) {
    return make_float2(a.x + b.x, a.y + b.y);
}

__device__ __forceinline__ long binom(int n, int k) {
    if (k < 0 || n < 0 || k > n) return 0;
    long r = 1;
    for (int i = 1; i <= k; i++) r = r * (n - k + i) / i;
    return r;
}

// ---------------------------------------------------------------------------
// Setup kernel: interferometers + Fock row tables (10 blocks x 256)
// ---------------------------------------------------------------------------
__global__ void setup_kernel(const float* __restrict__ ph_l1,
                             const float* __restrict__ ph_r1,
                             const float* __restrict__ ph_lf,
                             const float* __restrict__ ph_rf) {
    if (blockIdx.x == 0) {
        __shared__ float2 T[4][45][4];
        int t = threadIdx.x;
        if (t < 180) {
            int g = t / 45, k = t % 45;
            const float* ph = (g == 0) ? ph_l1 : (g == 1) ? ph_r1 : (g == 2) ? ph_lf : ph_rf;
            float t1 = ph[2 * k], t2 = ph[2 * k + 1];
            float s1, c1, s2, c2v;
            sincosf(t1, &s1, &c1);
            sincosf(t2, &s2, &c2v);
            float2 e1 = make_float2(c1, s1), e2 = make_float2(c2v, s2);
            const float s = 0.7071067811865476f;
            float2 B00 = make_float2(s, 0), B01 = make_float2(0, s);
            float2 B10 = make_float2(0, s), B11 = make_float2(s, 0);
            float2 M100 = cmul(e1, B00), M101 = cmul(e1, B01);
            float2 M110 = B10, M111 = B11;
            float2 M200 = cadd(cmul(B00, M100), cmul(B01, M110));
            float2 M201 = cadd(cmul(B00, M101), cmul(B01, M111));
            float2 M210 = cadd(cmul(B10, M100), cmul(B11, M110));
            float2 M211 = cadd(cmul(B10, M101), cmul(B11, M111));
            T[g][k][0] = cmul(e2, M200);
            T[g][k][1] = cmul(e2, M201);
            T[g][k][2] = M210;
            T[g][k][3] = M211;
        }
        __syncthreads();
        if (t < 40) {
            int g = t / 10, col = t % 10;
            float2 u[10];
            #pragma unroll
            for (int m = 0; m < 10; m++) u[m] = make_float2(m == col ? 1.f : 0.f, 0.f);
            int k = 0;
            for (int layer = 0; layer < 10; layer++) {
                for (int p = (layer & 1); p < 9; p += 2) {
                    float2 a = u[p], b = u[p + 1];
                    u[p]     = cadd(cmul(T[g][k][0], a), cmul(T[g][k][1], b));
                    u[p + 1] = cadd(cmul(T[g][k][2], a), cmul(T[g][k][3], b));
                    k++;
                }
            }
            if (g == 0) {
                if ((col & 1) == 0)
                    for (int m = 0; m < 10; m++) g_WL1c[m][col >> 1] = u[m];
            } else if (g == 1) {
                for (int m = 0; m < 10; m++) g_WR1[m][col] = u[m];
            } else if (g == 2) {
                if ((col & 1) == 0)
                    for (int m = 0; m < 10; m++) g_WLFc[m][col >> 1] = u[m];
            } else {
                for (int m = 0; m < 10; m++) g_WRF[m][col] = u[m];
            }
        }
    } else {
        int idx = (blockIdx.x - 1) * blockDim.x + threadIdx.x;
        if (idx < N_NB) {
            int r = idx, x = 0;
            unsigned packed = 0;
            for (int pos = 0; pos < 5; pos++) {
                for (;;) {
                    long cnt = binom(9 - x, 4 - pos);
                    if (r < cnt) break;
                    r -= (int)cnt;
                    x++;
                }
                packed |= (unsigned)x << (4 * pos);
                x++;
            }
            g_rows_nb[idx] = packed;
        } else if (idx < N_NB + N_B) {
            int rank = idx - N_NB;
            int r = rank, x = 0;
            int row[5];
            for (int pos = 0; pos < 5; pos++) {
                for (;;) {
                    long cnt = binom(13 - x, 4 - pos);
                    if (r < cnt) break;
                    r -= (int)cnt;
                    x++;
                }
                row[pos] = x - pos;
                x++;
            }
            unsigned packed = 0;
            int cnt_[10];
            #pragma unroll
            for (int m = 0; m < 10; m++) cnt_[m] = 0;
            #pragma unroll
            for (int pos = 0; pos < 5; pos++) {
                packed |= (unsigned)row[pos] << (4 * pos);
                cnt_[row[pos]]++;
            }
            const float fact[6] = {1.f, 1.f, 2.f, 6.f, 24.f, 120.f};
            float norm = 1.f;
            #pragma unroll
            for (int m = 0; m < 10; m++) norm *= fact[cnt_[m]];
            g_rows_b[rank] = packed;
            g_inv_norm_b[rank] = 1.0f / norm;
        }
    }
}

// ---------------------------------------------------------------------------
// Glynn |perm|^2, single matrix (used for the 252 no-bunching phase).
// ---------------------------------------------------------------------------
__device__ __forceinline__ float perm_prob(const float2 (*__restrict__ V)[5], unsigned packed) {
    float2 M[5][5];
    #pragma unroll
    for (int i = 0; i < 5; i++) {
        int ri = (packed >> (4 * i)) & 15;
        #pragma unroll
        for (int j = 0; j < 5; j++) M[i][j] = V[ri][j];
    }
    float2 rs[5];
    #pragma unroll
    for (int j = 0; j < 5; j++) {
        rs[j].x = M[0][j].x + M[1][j].x + M[2][j].x + M[3][j].x + M[4][j].x;
        rs[j].y = M[0][j].y + M[1][j].y + M[2][j].y + M[3][j].y + M[4][j].y;
    }
    float sx = 0.f, sy = 0.f;
    #pragma unroll
    for (int g = 0; g < 16; g++) {
        float2 p01 = cmul(rs[0], rs[1]);
        float2 p23 = cmul(rs[2], rs[3]);
        float2 p = cmul(cmul(p01, p23), rs[4]);
        if (g & 1) { sx -= p.x; sy -= p.y; }
        else       { sx += p.x; sy += p.y; }
        if (g < 15) {
            int gc = g ^ (g >> 1);
            int gn = (g + 1) ^ ((g + 1) >> 1);
            int diff = gc ^ gn;
            int i = __ffs(diff);   // row 1..4, compile-time after unroll
            float dlt = (gn & diff) ? -2.f : 2.f;
            #pragma unroll
            for (int j = 0; j < 5; j++) {
                rs[j].x = fmaf(dlt, M[i][j].x, rs[j].x);
                rs[j].y = fmaf(dlt, M[i][j].y, rs[j].y);
            }
        }
    }
    sx *= 0.0625f;
    sy *= 0.0625f;
    return fmaf(sx, sx, sy * sy);
}

// ---------------------------------------------------------------------------
// Dual Glynn |perm|^2: two independent permanents interleaved for ILP.
// Rows 1,2 (hot in Gray schedule: 8x,4x) live in registers; rows 3,4 (2x,1x)
// are re-read from shared at use sites to bound register pressure.
// ---------------------------------------------------------------------------
__device__ __forceinline__ void perm_prob_dual(const float2 (*__restrict__ V)[5],
                                               unsigned pa, unsigned pb,
                                               float& outA, float& outB) {
    int ra0 =  pa        & 15, ra1 = (pa >> 4)  & 15, ra2 = (pa >> 8)  & 15;
    int ra3 = (pa >> 12) & 15, ra4 = (pa >> 16) & 15;
    int rb0 =  pb        & 15, rb1 = (pb >> 4)  & 15, rb2 = (pb >> 8)  & 15;
    int rb3 = (pb >> 12) & 15, rb4 = (pb >> 16) & 15;

    float2 MA1[5], MA2[5], MB1[5], MB2[5];
    float2 rsA[5], rsB[5];
    #pragma unroll
    for (int j = 0; j < 5; j++) {
        float2 a1 = V[ra1][j], a2 = V[ra2][j];
        MA1[j] = a1; MA2[j] = a2;
        float2 a0 = V[ra0][j], a3 = V[ra3][j], a4 = V[ra4][j];
        rsA[j].x = a0.x + a1.x + a2.x + a3.x + a4.x;
        rsA[j].y = a0.y + a1.y + a2.y + a3.y + a4.y;
        float2 b1 = V[rb1][j], b2 = V[rb2][j];
        MB1[j] = b1; MB2[j] = b2;
        float2 b0 = V[rb0][j], b3 = V[rb3][j], b4 = V[rb4][j];
        rsB[j].x = b0.x + b1.x + b2.x + b3.x + b4.x;
        rsB[j].y = b0.y + b1.y + b2.y + b3.y + b4.y;
    }

    float sxA = 0.f, syA = 0.f, sxB = 0.f, syB = 0.f;
    #pragma unroll
    for (int g = 0; g < 16; g++) {
        {
            float2 p01 = cmul(rsA[0], rsA[1]);
            float2 p23 = cmul(rsA[2], rsA[3]);
            float2 p = cmul(cmul(p01, p23), rsA[4]);
            if (g & 1) { sxA -= p.x; syA -= p.y; }
            else       { sxA += p.x; syA += p.y; }
        }
        {
            float2 p01 = cmul(rsB[0], rsB[1]);
            float2 p23 = cmul(rsB[2], rsB[3]);
            float2 p = cmul(cmul(p01, p23), rsB[4]);
            if (g & 1) { sxB -= p.x; syB -= p.y; }
            else       { sxB += p.x; syB += p.y; }
        }
        if (g < 15) {
            int gc = g ^ (g >> 1);
            int gn = (g + 1) ^ ((g + 1) >> 1);
            int diff = gc ^ gn;
            int r = __ffs(diff);                       // 1..4, compile-time
            float dlt = (gn & diff) ? -2.f : 2.f;
            #pragma unroll
            for (int j = 0; j < 5; j++) {
                float2 ma, mb;
                if (r == 1)      { ma = MA1[j];     mb = MB1[j]; }
                else if (r == 2) { ma = MA2[j];     mb = MB2[j]; }
                else if (r == 3) { ma = V[ra3][j];  mb = V[rb3][j]; }
                else             { ma = V[ra4][j];  mb = V[rb4][j]; }
                rsA[j].x = fmaf(dlt, ma.x, rsA[j].x);
                rsA[j].y = fmaf(dlt, ma.y, rsA[j].y);
                rsB[j].x = fmaf(dlt, mb.x, rsB[j].x);
                rsB[j].y = fmaf(dlt, mb.y, rsB[j].y);
            }
        }
    }
    sxA *= 0.0625f; syA *= 0.0625f;
    sxB *= 0.0625f; syB *= 0.0625f;
    outA = fmaf(sxA, sxA, syA * syA);
    outB = fmaf(sxB, sxB, syB * syB);
}

// ---------------------------------------------------------------------------
// Fused main kernel: one block per batch element, 512 threads.
// ---------------------------------------------------------------------------
__global__ __launch_bounds__(512, 1)
void qc_main(const float* __restrict__ x, const float* __restrict__ Wd,
             const float* __restrict__ bd, const float* __restrict__ Wo,
             const float* __restrict__ bo, float* __restrict__ out) {
    int b = blockIdx.x;
    int t = threadIdx.x;
    int lane = t & 31;
    int w = t >> 5;   // 16 warps

    __shared__ float2 sh_eih[10];
    __shared__ float2 sh_V[10][5];
    __shared__ float  sh_e1[N_NB];
    __shared__ float  sh_red[16][10];

    // 1. h = (x@Wd + bd)/pi, warp w computes output mode w (w < 10)
    if (w < 10) {
        float acc = 0.f;
        const float* xb = x + b * 784;
        for (int i = lane; i < 784; i += 32) acc = fmaf(xb[i], Wd[i * 10 + w], acc);
        #pragma unroll
        for (int o = 16; o; o >>= 1) acc += __shfl_xor_sync(0xffffffffu, acc, o);
        if (lane == 0) {
            float h = (acc + bd[w]) * 0.3183098861837907f;  // 1/pi
            float sn, cs;
            sincosf(h, &sn, &cs);
            sh_eih[w] = make_float2(cs, sn);
        }
    }
    __syncthreads();

    // 2. V1[m][j] = sum_k WR1[m][k] * e^{ih_k} * WL1c[k][j]
    if (t < 50) {
        int m = t / 5, j = t % 5;
        float2 v = make_float2(0.f, 0.f);
        #pragma unroll
        for (int k = 0; k < 10; k++)
            v = cadd(v, cmul(g_WR1[m][k], cmul(sh_eih[k], g_WL1c[k][j])));
        sh_V[m][j] = v;
    }
    __syncthreads();

    // 3. 252 no-bunching probabilities (norm = 1)
    if (t < N_NB) sh_e1[t] = perm_prob(sh_V, g_rows_nb[t]);
    __syncthreads();

    // 4. phi2[m] = sum_j e1[m + 10j]; then e^{i phi2}
    if (t < 10) {
        float phi = 0.f;
        for (int j2 = t; j2 < N_NB; j2 += 10) phi += sh_e1[j2];
        float sn, cs;
        sincosf(phi, &sn, &cs);
        sh_eih[t] = make_float2(cs, sn);
    }
    __syncthreads();

    // 5. VF[m][j]
    if (t < 50) {
        int m = t / 5, j = t % 5;
        float2 v = make_float2(0.f, 0.f);
        #pragma unroll
        for (int k = 0; k < 10; k++)
            v = cadd(v, cmul(g_WRF[m][k], cmul(sh_eih[k], g_WLFc[k][j])));
        sh_V[m][j] = v;
    }
    __syncthreads();

    // 6. 2002 bunched perms, 2-way ILP, fused with probs @ W_out
    float acc[10];
    #pragma unroll
    for (int c = 0; c < 10; c++) acc[c] = 0.f;

    {   // pair 0: k = t, t+512 (both always valid; max 1023 < 2002)
        int kA = t, kB = t + 512;
        float pA, pB;
        perm_prob_dual(sh_V, g_rows_b[kA], g_rows_b[kB], pA, pB);
        pA *= g_inv_norm_b[kA];
        pB *= g_inv_norm_b[kB];
        const float* wa = Wo + kA * 10;
        const float* wb = Wo + kB * 10;
        #pragma unroll
        for (int c = 0; c < 10; c++) {
            acc[c] = fmaf(pA, wa[c], acc[c]);
            acc[c] = fmaf(pB, wb[c], acc[c]);
        }
    }
    {   // pair 1: k = t+1024 (always valid; max 1535), t+1536 (valid iff t<466)
        int kA = t + 1024, kB = t + 1536;
        if (kB < N_B) {
            float pA, pB;
            perm_prob_dual(sh_V, g_rows_b[kA], g_rows_b[kB], pA, pB);
            pA *= g_inv_norm_b[kA];
            pB *= g_inv_norm_b[kB];
            const float* wa = Wo + kA * 10;
            const float* wb = Wo + kB * 10;
            #pragma unroll
            for (int c = 0; c < 10; c++) {
                acc[c] = fmaf(pA, wa[c], acc[c]);
                acc[c] = fmaf(pB, wb[c], acc[c]);
            }
        } else {
            float pA = perm_prob(sh_V, g_rows_b[kA]) * g_inv_norm_b[kA];
            const float* wa = Wo + kA * 10;
            #pragma unroll
            for (int c = 0; c < 10; c++) acc[c] = fmaf(pA, wa[c], acc[c]);
        }
    }

    #pragma unroll
    for (int c = 0; c < 10; c++) {
        #pragma unroll
        for (int o = 16; o; o >>= 1) acc[c] += __shfl_xor_sync(0xffffffffu, acc[c], o);
    }
    if (lane == 0) {
        #pragma unroll
        for (int c = 0; c < 10; c++) sh_red[w][c] = acc[c];
    }
    __syncthreads();
    if (t < 10) {
        float v = bo[t];
        #pragma unroll
        for (int ww = 0; ww < 16; ww++) v += sh_red[ww][t];
        out[b * 10 + t] = v;
    }
}

// ---------------------------------------------------------------------------
extern "C" void kernel_launch(void* const* d_in, const int* in_sizes, int n_in,
                              void* d_out, int out_size) {
    const float* x   = (const float*)d_in[0];
    const float* Wd  = (const float*)d_in[1];
    const float* bd  = (const float*)d_in[2];
    const float* pl1 = (const float*)d_in[3];
    const float* pr1 = (const float*)d_in[4];
    const float* plf = (const float*)d_in[5];
    const float* prf = (const float*)d_in[6];
    const float* Wo  = (const float*)d_in[7];
    const float* bo  = (const float*)d_in[8];
    float* out = (float*)d_out;

    int B = in_sizes[0] / 784;

    setup_kernel<<<10, 256>>>(pl1, pr1, plf, prf);
    qc_main<<<B, 512>>>(x, Wd, bd, Wo, bo, out);
}

// round 6
// speedup vs baseline: 1.8007x; 1.0923x over previous
#include <cuda_runtime.h>
#include <cstdint>

// ---------------------------------------------------------------------------
#define M_MODES 10
#define N_PHOT  5
#define N_NB    252     // C(10,5)
#define N_B     2002    // C(14,5)

// ---------------------------------------------------------------------------
// Compile-time Fock tables (input-independent): packed rows + 1/norm.
// ---------------------------------------------------------------------------
struct Tables {
    unsigned nb[N_NB];
    unsigned bb[N_B];
    float    inv_norm[N_B];
};

constexpr unsigned pack5(int a, int b, int c, int d, int e) {
    return (unsigned)a | ((unsigned)b << 4) | ((unsigned)c << 8) |
           ((unsigned)d << 12) | ((unsigned)e << 16);
}

constexpr Tables make_tables() {
    Tables T{};
    int i = 0;
    for (int a = 0; a < 10; a++)
        for (int b = a + 1; b < 10; b++)
            for (int c = b + 1; c < 10; c++)
                for (int d = c + 1; d < 10; d++)
                    for (int e = d + 1; e < 10; e++)
                        T.nb[i++] = pack5(a, b, c, d, e);
    i = 0;
    for (int a = 0; a < 10; a++)
        for (int b = a; b < 10; b++)
            for (int c = b; c < 10; c++)
                for (int d = c; d < 10; d++)
                    for (int e = d; e < 10; e++) {
                        T.bb[i] = pack5(a, b, c, d, e);
                        int cnt[10] = {};
                        cnt[a]++; cnt[b]++; cnt[c]++; cnt[d]++; cnt[e]++;
                        float fact[6] = {1.f, 1.f, 2.f, 6.f, 24.f, 120.f};
                        float norm = 1.f;
                        for (int m = 0; m < 10; m++) norm *= fact[cnt[m]];
                        T.inv_norm[i] = 1.0f / norm;
                        i++;
                    }
    return T;
}

__device__ constexpr Tables g_tab = make_tables();

// ---------------------------------------------------------------------------
__device__ __forceinline__ float2 cmul(float2 a, float2 b) {
    return make_float2(fmaf(a.x, b.x, -a.y * b.y), fmaf(a.x, b.y, a.y * b.x));
}
__device__ __forceinline__ float2 cadd(float2 a, float2 b) {
    return make_float2(a.x + b.x, a.y + b.y);
}

// ---------------------------------------------------------------------------
// Glynn |perm|^2, single matrix.
// ---------------------------------------------------------------------------
__device__ __forceinline__ float perm_prob(const float2 (*__restrict__ V)[5], unsigned packed) {
    float2 M[5][5];
    #pragma unroll
    for (int i = 0; i < 5; i++) {
        int ri = (packed >> (4 * i)) & 15;
        #pragma unroll
        for (int j = 0; j < 5; j++) M[i][j] = V[ri][j];
    }
    float2 rs[5];
    #pragma unroll
    for (int j = 0; j < 5; j++) {
        rs[j].x = M[0][j].x + M[1][j].x + M[2][j].x + M[3][j].x + M[4][j].x;
        rs[j].y = M[0][j].y + M[1][j].y + M[2][j].y + M[3][j].y + M[4][j].y;
    }
    float sx = 0.f, sy = 0.f;
    #pragma unroll
    for (int g = 0; g < 16; g++) {
        float2 p01 = cmul(rs[0], rs[1]);
        float2 p23 = cmul(rs[2], rs[3]);
        float2 p = cmul(cmul(p01, p23), rs[4]);
        if (g & 1) { sx -= p.x; sy -= p.y; }
        else       { sx += p.x; sy += p.y; }
        if (g < 15) {
            int gc = g ^ (g >> 1);
            int gn = (g + 1) ^ ((g + 1) >> 1);
            int diff = gc ^ gn;
            int i = __ffs(diff);   // 1..4, compile-time after unroll
            float dlt = (gn & diff) ? -2.f : 2.f;
            #pragma unroll
            for (int j = 0; j < 5; j++) {
                rs[j].x = fmaf(dlt, M[i][j].x, rs[j].x);
                rs[j].y = fmaf(dlt, M[i][j].y, rs[j].y);
            }
        }
    }
    sx *= 0.0625f;
    sy *= 0.0625f;
    return fmaf(sx, sx, sy * sy);
}

// ---------------------------------------------------------------------------
// Dual Glynn |perm|^2: two independent permanents interleaved for ILP.
// ---------------------------------------------------------------------------
__device__ __forceinline__ void perm_prob_dual(const float2 (*__restrict__ V)[5],
                                               unsigned pa, unsigned pb,
                                               float& outA, float& outB) {
    int ra0 =  pa        & 15, ra1 = (pa >> 4)  & 15, ra2 = (pa >> 8)  & 15;
    int ra3 = (pa >> 12) & 15, ra4 = (pa >> 16) & 15;
    int rb0 =  pb        & 15, rb1 = (pb >> 4)  & 15, rb2 = (pb >> 8)  & 15;
    int rb3 = (pb >> 12) & 15, rb4 = (pb >> 16) & 15;

    float2 MA1[5], MA2[5], MB1[5], MB2[5];
    float2 rsA[5], rsB[5];
    #pragma unroll
    for (int j = 0; j < 5; j++) {
        float2 a1 = V[ra1][j], a2 = V[ra2][j];
        MA1[j] = a1; MA2[j] = a2;
        float2 a0 = V[ra0][j], a3 = V[ra3][j], a4 = V[ra4][j];
        rsA[j].x = a0.x + a1.x + a2.x + a3.x + a4.x;
        rsA[j].y = a0.y + a1.y + a2.y + a3.y + a4.y;
        float2 b1 = V[rb1][j], b2 = V[rb2][j];
        MB1[j] = b1; MB2[j] = b2;
        float2 b0 = V[rb0][j], b3 = V[rb3][j], b4 = V[rb4][j];
        rsB[j].x = b0.x + b1.x + b2.x + b3.x + b4.x;
        rsB[j].y = b0.y + b1.y + b2.y + b3.y + b4.y;
    }

    float sxA = 0.f, syA = 0.f, sxB = 0.f, syB = 0.f;
    #pragma unroll
    for (int g = 0; g < 16; g++) {
        {
            float2 p01 = cmul(rsA[0], rsA[1]);
            float2 p23 = cmul(rsA[2], rsA[3]);
            float2 p = cmul(cmul(p01, p23), rsA[4]);
            if (g & 1) { sxA -= p.x; syA -= p.y; }
            else       { sxA += p.x; syA += p.y; }
        }
        {
            float2 p01 = cmul(rsB[0], rsB[1]);
            float2 p23 = cmul(rsB[2], rsB[3]);
            float2 p = cmul(cmul(p01, p23), rsB[4]);
            if (g & 1) { sxB -= p.x; syB -= p.y; }
            else       { sxB += p.x; syB += p.y; }
        }
        if (g < 15) {
            int gc = g ^ (g >> 1);
            int gn = (g + 1) ^ ((g + 1) >> 1);
            int diff = gc ^ gn;
            int r = __ffs(diff);                       // 1..4, compile-time
            float dlt = (gn & diff) ? -2.f : 2.f;
            #pragma unroll
            for (int j = 0; j < 5; j++) {
                float2 ma, mb;
                if (r == 1)      { ma = MA1[j];     mb = MB1[j]; }
                else if (r == 2) { ma = MA2[j];     mb = MB2[j]; }
                else if (r == 3) { ma = V[ra3][j];  mb = V[rb3][j]; }
                else             { ma = V[ra4][j];  mb = V[rb4][j]; }
                rsA[j].x = fmaf(dlt, ma.x, rsA[j].x);
                rsA[j].y = fmaf(dlt, ma.y, rsA[j].y);
                rsB[j].x = fmaf(dlt, mb.x, rsB[j].x);
                rsB[j].y = fmaf(dlt, mb.y, rsB[j].y);
            }
        }
    }
    sxA *= 0.0625f; syA *= 0.0625f;
    sxB *= 0.0625f; syB *= 0.0625f;
    outA = fmaf(sxA, sxA, syA * syA);
    outB = fmaf(sxB, sxB, syB * syB);
}

// ---------------------------------------------------------------------------
// Single fused kernel: one block per batch element, 512 threads.
// Warps 0-9: input projection. Warps 10-15: build the 4 interferometers
// (overlapped). Then permanents as before.
// ---------------------------------------------------------------------------
__global__ __launch_bounds__(512, 1)
void qc_main(const float* __restrict__ x, const float* __restrict__ Wd,
             const float* __restrict__ bd,
             const float* __restrict__ ph_l1, const float* __restrict__ ph_r1,
             const float* __restrict__ ph_lf, const float* __restrict__ ph_rf,
             const float* __restrict__ Wo, const float* __restrict__ bo,
             float* __restrict__ out) {
    int b = blockIdx.x;
    int t = threadIdx.x;
    int lane = t & 31;
    int w = t >> 5;   // 16 warps

    __shared__ float2 sh_T[4][45][4];
    __shared__ float2 sh_WR1[10][10];
    __shared__ float2 sh_WL1c[10][5];
    __shared__ float2 sh_WRF[10][10];
    __shared__ float2 sh_WLFc[10][5];
    __shared__ float2 sh_eih[10];
    __shared__ float2 sh_V[10][5];
    __shared__ float  sh_e1[N_NB];
    __shared__ float  sh_red[16][10];

    if (t >= 320) {
        // ---- interferometer build on warps 10-15 (192 threads) ----
        int l = t - 320;
        if (l < 180) {
            int g = l / 45, k = l % 45;
            const float* ph = (g == 0) ? ph_l1 : (g == 1) ? ph_r1 : (g == 2) ? ph_lf : ph_rf;
            float t1 = ph[2 * k], t2 = ph[2 * k + 1];
            float s1, c1, s2, c2v;
            sincosf(t1, &s1, &c1);
            sincosf(t2, &s2, &c2v);
            float2 e1 = make_float2(c1, s1), e2 = make_float2(c2v, s2);
            const float s = 0.7071067811865476f;
            float2 B00 = make_float2(s, 0), B01 = make_float2(0, s);
            float2 B10 = make_float2(0, s), B11 = make_float2(s, 0);
            float2 M100 = cmul(e1, B00), M101 = cmul(e1, B01);
            float2 M110 = B10, M111 = B11;
            float2 M200 = cadd(cmul(B00, M100), cmul(B01, M110));
            float2 M201 = cadd(cmul(B00, M101), cmul(B01, M111));
            float2 M210 = cadd(cmul(B10, M100), cmul(B11, M110));
            float2 M211 = cadd(cmul(B10, M101), cmul(B11, M111));
            sh_T[g][k][0] = cmul(e2, M200);
            sh_T[g][k][1] = cmul(e2, M201);
            sh_T[g][k][2] = M210;
            sh_T[g][k][3] = M211;
        }
        asm volatile("bar.sync 1, 192;" ::: "memory");
        if (l < 40) {
            int g = l / 10, col = l % 10;
            float2 u[10];
            #pragma unroll
            for (int m = 0; m < 10; m++) u[m] = make_float2(m == col ? 1.f : 0.f, 0.f);
            int k = 0;
            for (int layer = 0; layer < 10; layer++) {
                for (int p = (layer & 1); p < 9; p += 2) {
                    float2 a = u[p], bb2 = u[p + 1];
                    u[p]     = cadd(cmul(sh_T[g][k][0], a), cmul(sh_T[g][k][1], bb2));
                    u[p + 1] = cadd(cmul(sh_T[g][k][2], a), cmul(sh_T[g][k][3], bb2));
                    k++;
                }
            }
            if (g == 0) {
                if ((col & 1) == 0)
                    for (int m = 0; m < 10; m++) sh_WL1c[m][col >> 1] = u[m];
            } else if (g == 1) {
                for (int m = 0; m < 10; m++) sh_WR1[m][col] = u[m];
            } else if (g == 2) {
                if ((col & 1) == 0)
                    for (int m = 0; m < 10; m++) sh_WLFc[m][col >> 1] = u[m];
            } else {
                for (int m = 0; m < 10; m++) sh_WRF[m][col] = u[m];
            }
        }
    } else if (w < 10) {
        // ---- projection: h = (x@Wd + bd)/pi, warp w -> mode w ----
        float acc = 0.f;
        const float* xb = x + b * 784;
        for (int i = lane; i < 784; i += 32) acc = fmaf(xb[i], Wd[i * 10 + w], acc);
        #pragma unroll
        for (int o = 16; o; o >>= 1) acc += __shfl_xor_sync(0xffffffffu, acc, o);
        if (lane == 0) {
            float h = (acc + bd[w]) * 0.3183098861837907f;  // 1/pi
            float sn, cs;
            sincosf(h, &sn, &cs);
            sh_eih[w] = make_float2(cs, sn);
        }
    }
    __syncthreads();

    // 2. V1[m][j] = sum_k WR1[m][k] * e^{ih_k} * WL1c[k][j]
    if (t < 50) {
        int m = t / 5, j = t % 5;
        float2 v = make_float2(0.f, 0.f);
        #pragma unroll
        for (int k = 0; k < 10; k++)
            v = cadd(v, cmul(sh_WR1[m][k], cmul(sh_eih[k], sh_WL1c[k][j])));
        sh_V[m][j] = v;
    }
    __syncthreads();

    // 3. 252 no-bunching probabilities, 2-way ILP (126 threads x dual)
    if (t < 126) {
        float pA, pB;
        perm_prob_dual(sh_V, g_tab.nb[t], g_tab.nb[t + 126], pA, pB);
        sh_e1[t] = pA;
        sh_e1[t + 126] = pB;
    }
    __syncthreads();

    // 4. phi2[m] = sum_j e1[m + 10j]; then e^{i phi2}
    if (t < 10) {
        float phi = 0.f;
        for (int j2 = t; j2 < N_NB; j2 += 10) phi += sh_e1[j2];
        float sn, cs;
        sincosf(phi, &sn, &cs);
        sh_eih[t] = make_float2(cs, sn);
    }
    __syncthreads();

    // 5. VF[m][j]
    if (t < 50) {
        int m = t / 5, j = t % 5;
        float2 v = make_float2(0.f, 0.f);
        #pragma unroll
        for (int k = 0; k < 10; k++)
            v = cadd(v, cmul(sh_WRF[m][k], cmul(sh_eih[k], sh_WLFc[k][j])));
        sh_V[m][j] = v;
    }
    __syncthreads();

    // 6. 2002 bunched perms, 2-way ILP, fused with probs @ W_out
    float acc[10];
    #pragma unroll
    for (int c = 0; c < 10; c++) acc[c] = 0.f;

    {   // pair 0: k = t, t+512
        int kA = t, kB = t + 512;
        float pA, pB;
        perm_prob_dual(sh_V, g_tab.bb[kA], g_tab.bb[kB], pA, pB);
        pA *= g_tab.inv_norm[kA];
        pB *= g_tab.inv_norm[kB];
        const float* wa = Wo + kA * 10;
        const float* wb = Wo + kB * 10;
        #pragma unroll
        for (int c = 0; c < 10; c++) {
            acc[c] = fmaf(pA, wa[c], acc[c]);
            acc[c] = fmaf(pB, wb[c], acc[c]);
        }
    }
    {   // pair 1: k = t+1024, t+1536 (latter valid iff t<466)
        int kA = t + 1024, kB = t + 1536;
        if (kB < N_B) {
            float pA, pB;
            perm_prob_dual(sh_V, g_tab.bb[kA], g_tab.bb[kB], pA, pB);
            pA *= g_tab.inv_norm[kA];
            pB *= g_tab.inv_norm[kB];
            const float* wa = Wo + kA * 10;
            const float* wb = Wo + kB * 10;
            #pragma unroll
            for (int c = 0; c < 10; c++) {
                acc[c] = fmaf(pA, wa[c], acc[c]);
                acc[c] = fmaf(pB, wb[c], acc[c]);
            }
        } else {
            float pA = perm_prob(sh_V, g_tab.bb[kA]) * g_tab.inv_norm[kA];
            const float* wa = Wo + kA * 10;
            #pragma unroll
            for (int c = 0; c < 10; c++) acc[c] = fmaf(pA, wa[c], acc[c]);
        }
    }

    #pragma unroll
    for (int c = 0; c < 10; c++) {
        #pragma unroll
        for (int o = 16; o; o >>= 1) acc[c] += __shfl_xor_sync(0xffffffffu, acc[c], o);
    }
    if (lane == 0) {
        #pragma unroll
        for (int c = 0; c < 10; c++) sh_red[w][c] = acc[c];
    }
    __syncthreads();
    if (t < 10) {
        float v = bo[t];
        #pragma unroll
        for (int ww = 0; ww < 16; ww++) v += sh_red[ww][t];
        out[b * 10 + t] = v;
    }
}

// ---------------------------------------------------------------------------
extern "C" void kernel_launch(void* const* d_in, const int* in_sizes, int n_in,
                              void* d_out, int out_size) {
    const float* x   = (const float*)d_in[0];
    const float* Wd  = (const float*)d_in[1];
    const float* bd  = (const float*)d_in[2];
    const float* pl1 = (const float*)d_in[3];
    const float* pr1 = (const float*)d_in[4];
    const float* plf = (const float*)d_in[5];
    const float* prf = (const float*)d_in[6];
    const float* Wo  = (const float*)d_in[7];
    const float* bo  = (const float*)d_in[8];
    float* out = (float*)d_out;

    int B = in_sizes[0] / 784;

    qc_main<<<B, 512>>>(x, Wd, bd, pl1, pr1, plf, prf, Wo, bo, out);
}